// round 4
// baseline (speedup 1.0000x reference)
#include <cuda_runtime.h>
#include <math.h>

// ----------------------------------------------------------------------------
// DARTS-style supernet forward:
//   states = [s0, s1, cat(s0,s1)]
//   node i (i=0..3): s = sum_j mixed(states[j], W_l, b_l, geno_l), l = offset+j
//   mixed(x,W,b,w) = sum_k w[k] * act_k(x @ W[k] + b[k]),  5 ops
// Output = node 3 result  [4096, 1024] fp32.
//
// This round: fused fp32 SGEMM per node. Each CTA computes a 128x128 tile of
// the node output; loops over (edge, op), runs full-K reduction in registers,
// applies bias + activation + genotype weight, accumulates into a second
// register tile. No intermediates in HBM, no atomics. "cat" edge reads s0 for
// k<1024 and s1 for k>=1024 (no concat buffer).
// ----------------------------------------------------------------------------

#define BM 128
#define BN 128
#define BK 16
#define NTHREADS 256

#define BATCH 4096
#define DDIM  1024

struct EdgeDesc {
    const float* xa;    // input for k <  ksplit
    const float* xb;    // input for k >= ksplit
    const float* W;     // [5, K, 1024]
    int K;              // 1024 or 2048
    int ksplit;         // 1024 (cat edge) or == K (normal edge)
    int layer;          // global layer index l (for genotype / bias)
};

struct NodeArgs {
    EdgeDesc e[6];
    int n_edges;
};

// Scratch for node outputs 0..2 (node 3 goes to d_out). Static device arrays
// per harness rules (no cudaMalloc anywhere).
__device__ float g_node0[BATCH * DDIM];
__device__ float g_node1[BATCH * DDIM];
__device__ float g_node2[BATCH * DDIM];

__global__ __launch_bounds__(NTHREADS, 1)
void node_kernel(NodeArgs args,
                 const float* __restrict__ geno,   // [18,5]
                 const float* __restrict__ bsv,    // [18,5,1024]
                 float* __restrict__ out)          // [4096,1024]
{
    __shared__ float As[BK][BM];   // x tile, transposed: As[k][m]
    __shared__ float Bs[BK][BN];   // W tile: Bs[k][n]

    const int bm = blockIdx.y * BM;
    const int bn = blockIdx.x * BN;
    const int tid = (int)threadIdx.x;
    const int tx = tid & 15;        // 16 thread-cols
    const int ty = tid >> 4;        // 16 thread-rows
    const int tm = ty * 8;
    const int tn = tx * 8;

    float accs[8][8];               // mixed-op accumulator (final tile)
    #pragma unroll
    for (int i = 0; i < 8; i++)
        #pragma unroll
        for (int j = 0; j < 8; j++)
            accs[i][j] = 0.0f;

    for (int e = 0; e < args.n_edges; e++) {
        const EdgeDesc ed = args.e[e];
        const int ntiles = ed.K / BK;

        for (int op = 0; op < 5; op++) {            // do NOT unroll: keeps I$ small
            const float* __restrict__ Wop = ed.W + (size_t)op * ed.K * DDIM;

            float acc[8][8];                        // per-(edge,op) GEMM accumulator
            #pragma unroll
            for (int i = 0; i < 8; i++)
                #pragma unroll
                for (int j = 0; j < 8; j++)
                    acc[i][j] = 0.0f;

            for (int kt = 0; kt < ntiles; kt++) {
                const int kg = kt * BK;
                const float* xbase = ed.xa;
                int koff = kg;
                if (kg >= ed.ksplit) { xbase = ed.xb; koff = kg - ed.ksplit; }

                // ---- load A tile: 128 rows x 16 k-cols (2 float4 per thread)
                #pragma unroll
                for (int rpt = 0; rpt < 2; rpt++) {
                    const int f  = tid + rpt * NTHREADS;   // 0..511
                    const int r  = f >> 2;                 // 0..127
                    const int c4 = f & 3;                  // 0..3
                    float4 v = *(const float4*)(xbase + (size_t)(bm + r) * DDIM + koff + c4 * 4);
                    As[c4 * 4 + 0][r] = v.x;
                    As[c4 * 4 + 1][r] = v.y;
                    As[c4 * 4 + 2][r] = v.z;
                    As[c4 * 4 + 3][r] = v.w;
                }
                // ---- load B tile: 16 k-rows x 128 cols (2 float4 per thread)
                #pragma unroll
                for (int rpt = 0; rpt < 2; rpt++) {
                    const int f  = tid + rpt * NTHREADS;   // 0..511
                    const int r  = f >> 5;                 // 0..15
                    const int c4 = f & 31;                 // 0..31
                    float4 v = *(const float4*)(Wop + (size_t)(kg + r) * DDIM + bn + c4 * 4);
                    *(float4*)&Bs[r][c4 * 4] = v;
                }
                __syncthreads();

                #pragma unroll
                for (int kk = 0; kk < BK; kk++) {
                    float a[8], b[8];
                    *(float4*)&a[0] = *(const float4*)&As[kk][tm];
                    *(float4*)&a[4] = *(const float4*)&As[kk][tm + 4];
                    *(float4*)&b[0] = *(const float4*)&Bs[kk][tn];
                    *(float4*)&b[4] = *(const float4*)&Bs[kk][tn + 4];
                    #pragma unroll
                    for (int i = 0; i < 8; i++)
                        #pragma unroll
                        for (int j = 0; j < 8; j++)
                            acc[i][j] = fmaf(a[i], b[j], acc[i][j]);
                }
                __syncthreads();
            }

            // ---- epilogue: h = acc + bias; accs += w * act_op(h)
            const float w = geno[ed.layer * 5 + op];
            const float* bp = bsv + (size_t)ed.layer * (5 * DDIM) + (size_t)op * DDIM + bn + tn;
            float bb[8];
            *(float4*)&bb[0] = *(const float4*)bp;
            *(float4*)&bb[4] = *(const float4*)(bp + 4);

            #pragma unroll
            for (int i = 0; i < 8; i++) {
                #pragma unroll
                for (int j = 0; j < 8; j++) {
                    const float h = acc[i][j] + bb[j];
                    float a;
                    if      (op == 0) a = h;
                    else if (op == 1) a = fmaxf(h, 0.0f);
                    else if (op == 2) a = tanhf(h);
                    else if (op == 3) a = 1.0f / (1.0f + expf(-h));
                    else              a = (h > 0.0f) ? h : 0.2f * h;
                    accs[i][j] = fmaf(w, a, accs[i][j]);
                }
            }
        }
    }

    // ---- write node output tile
    #pragma unroll
    for (int i = 0; i < 8; i++) {
        float* o = out + (size_t)(bm + tm + i) * DDIM + bn + tn;
        *(float4*)o       = *(const float4*)&accs[i][0];
        *(float4*)(o + 4) = *(const float4*)&accs[i][4];
    }
}

extern "C" void kernel_launch(void* const* d_in, const int* in_sizes, int n_in,
                              void* d_out, int out_size)
{
    // Identify inputs by element count (robust to any metadata ambiguity).
    const float *s0 = nullptr, *s1 = nullptr, *geno = nullptr;
    const float *Ws = nullptr, *Wb = nullptr, *bsv = nullptr;
    for (int i = 0; i < n_in; i++) {
        const long sz = (long)in_sizes[i];
        const float* p = (const float*)d_in[i];
        if      (sz == (long)BATCH * DDIM)            { if (!s0) s0 = p; else s1 = p; }
        else if (sz == 90L)                            geno = p;
        else if (sz == 14L * 5 * 1024 * 1024)          Ws   = p;
        else if (sz == 4L * 5 * 2048 * 1024)           Wb   = p;
        else if (sz == 18L * 5 * 1024)                 bsv  = p;
    }

    float *n0, *n1, *n2;
    cudaGetSymbolAddress((void**)&n0, g_node0);
    cudaGetSymbolAddress((void**)&n1, g_node1);
    cudaGetSymbolAddress((void**)&n2, g_node2);

    // states index j -> input pointer (j==2 is the cat edge, handled specially)
    const float* states[6] = { s0, s1, nullptr, n0, n1, n2 };
    float* outs[4] = { n0, n1, n2, (float*)d_out };

    dim3 grid(DDIM / BN, BATCH / BM);   // (8, 32) = 256 CTAs
    dim3 block(NTHREADS);

    int si = 0, bi = 0, offset = 0;
    for (int node = 0; node < 4; node++) {
        NodeArgs na;
        na.n_edges = node + 3;
        for (int j = 0; j < node + 3; j++) {
            EdgeDesc& ed = na.e[j];
            ed.layer = offset + j;
            if (j == 2) {
                ed.W = Wb + (size_t)bi * 5 * 2048 * 1024; bi++;
                ed.K = 2048; ed.ksplit = 1024;
                ed.xa = s0; ed.xb = s1;
            } else {
                ed.W = Ws + (size_t)si * 5 * 1024 * 1024; si++;
                ed.K = 1024; ed.ksplit = 1024;
                ed.xa = states[j]; ed.xb = states[j];
            }
        }
        node_kernel<<<grid, block>>>(na, geno, bsv, outs[node]);
        offset += node + 3;
    }
}

// round 6
// speedup vs baseline: 3.4865x; 3.4865x over previous
#include <cuda_runtime.h>
#include <cuda.h>
#include <cuda_bf16.h>
#include <math.h>
#include <stdint.h>

#define BATCH 4096
#define DDIM  1024
#define NSTAGE 3
#define STAGE  65536u
#define DYN_SMEM (1024u + 1024u + NSTAGE * STAGE)

// ------------------------- device scratch (no cudaMalloc) -------------------
__device__ __nv_bfloat16 g_ws_hi[73400320];   // [14*5][n=1024][k=1024]
__device__ __nv_bfloat16 g_ws_lo[73400320];
__device__ __nv_bfloat16 g_wb_hi[41943040];   // [4*5][n=1024][k=2048]
__device__ __nv_bfloat16 g_wb_lo[41943040];
__device__ __nv_bfloat16 g_x_hi[5][4194304];  // s0,s1,n0,n1,n2: [4096][1024]
__device__ __nv_bfloat16 g_x_lo[5][4194304];

// ------------------------------ PTX helpers ---------------------------------
__device__ __forceinline__ uint32_t smem_u32(const void* p) {
    uint32_t a;
    asm("{ .reg .u64 t; cvta.to.shared.u64 t, %1; cvt.u32.u64 %0, t; }"
        : "=r"(a) : "l"(p));
    return a;
}

#define MBAR_INIT(addr, cnt) \
    asm volatile("mbarrier.init.shared.b64 [%0], %1;" :: "r"(addr), "r"((uint32_t)(cnt)) : "memory")
#define MBAR_EXPECT_TX(addr, bytes) \
    asm volatile("mbarrier.arrive.expect_tx.shared.b64 _, [%0], %1;" :: "r"(addr), "r"((uint32_t)(bytes)) : "memory")
#define MBAR_ARRIVE(addr) \
    asm volatile("mbarrier.arrive.shared.b64 _, [%0];" :: "r"(addr) : "memory")
#define MBAR_WAIT(addr, ph) do {                                              \
    asm volatile(                                                             \
        "{\n\t.reg .pred P1;\n\t"                                             \
        "WL_%=:\n\t"                                                          \
        "mbarrier.try_wait.parity.acquire.cta.shared::cta.b64 P1, [%0], %1, 0x989680;\n\t" \
        "@P1 bra.uni WD_%=;\n\t"                                              \
        "bra.uni WL_%=;\n\t"                                                  \
        "WD_%=:\n\t}"                                                         \
        :: "r"((uint32_t)(addr)), "r"((uint32_t)(ph)) : "memory");            \
} while (0)

#define TMA2D(smaddr, map, cx, cy, mbar) \
    asm volatile("cp.async.bulk.tensor.2d.shared::cta.global.tile.mbarrier::complete_tx::bytes " \
                 "[%0], [%1, {%2, %3}], [%4];" \
                 :: "r"(smaddr), "l"(map), "r"(cx), "r"(cy), "r"(mbar) : "memory")

__device__ __forceinline__ void ldsm4(uint32_t addr, uint32_t r[4]) {
    asm volatile("ldmatrix.sync.aligned.m8n8.x4.shared.b16 {%0,%1,%2,%3}, [%4];"
        : "=r"(r[0]), "=r"(r[1]), "=r"(r[2]), "=r"(r[3]) : "r"(addr));
}

__device__ __forceinline__ void mma16816(float c[4], const uint32_t a[4],
                                         uint32_t b0, uint32_t b1) {
    asm volatile("mma.sync.aligned.m16n8k16.row.col.f32.bf16.bf16.f32 "
        "{%0,%1,%2,%3}, {%4,%5,%6,%7}, {%8,%9}, {%0,%1,%2,%3};"
        : "+f"(c[0]), "+f"(c[1]), "+f"(c[2]), "+f"(c[3])
        : "r"(a[0]), "r"(a[1]), "r"(a[2]), "r"(a[3]), "r"(b0), "r"(b1));
}

// ------------------------------- structs ------------------------------------
struct EdgeInfo {
    int a0, a1;        // g_x index for k<1024 / k>=1024
    int b_is_wb;       // 0: g_ws, 1: g_wb
    int b_row_base;    // tensor-local row base (idx*5*1024)
    int K;             // 1024 or 2048
    int layer;         // global layer index
};
struct NodeP {
    CUtensorMap a_hi[5];
    CUtensorMap a_lo[5];
    CUtensorMap ws_hi, ws_lo, wb_hi, wb_lo;
    EdgeInfo e[6];
    int n_edges;
    int node_out_idx;  // 2..4 -> g_x dest, -1 -> final fp32 out
};

// --------------------------- conversion kernels -----------------------------
__global__ void cvt_in(const float* __restrict__ s, int idx) {
    int i = blockIdx.x * 256 + threadIdx.x;
    float v = s[i];
    __nv_bfloat16 h = __float2bfloat16(v);
    g_x_hi[idx][i] = h;
    g_x_lo[idx][i] = __float2bfloat16(v - __bfloat162float(h));
}

// src: [Z][K][1024] fp32 -> dst: [Z][1024][K] bf16 hi/lo (transpose)
__global__ void cvt_w(const float* __restrict__ src,
                      __nv_bfloat16* __restrict__ hi,
                      __nv_bfloat16* __restrict__ lo, int K) {
    __shared__ float t[32][33];
    const int z = blockIdx.z;
    const int k0 = blockIdx.x * 32, n0 = blockIdx.y * 32;
    const int tx = threadIdx.x, ty = threadIdx.y;   // (32, 8)
    const float* s = src + (size_t)z * K * 1024;
    #pragma unroll
    for (int r = 0; r < 4; r++)
        t[ty + 8 * r][tx] = s[(size_t)(k0 + ty + 8 * r) * 1024 + n0 + tx];
    __syncthreads();
    const size_t dbase = (size_t)z * 1024 * K;
    #pragma unroll
    for (int r = 0; r < 4; r++) {
        const int n = n0 + ty + 8 * r, k = k0 + tx;
        const float v = t[tx][ty + 8 * r];
        const __nv_bfloat16 h = __float2bfloat16(v);
        hi[dbase + (size_t)n * K + k] = h;
        lo[dbase + (size_t)n * K + k] = __float2bfloat16(v - __bfloat162float(h));
    }
}

// ------------------------------ GEMM kernel ---------------------------------
__global__ void __launch_bounds__(256, 1)
gemm_node(const __grid_constant__ NodeP P,
          const float* __restrict__ geno,
          const float* __restrict__ bsv,
          float* __restrict__ outp)
{
    extern __shared__ char dynsmem[];
    const uint32_t sb = smem_u32(dynsmem);
    const uint32_t tile0 = (sb + 2047u) & ~1023u;
    float* sbias = (float*)(dynsmem + 256);
    const int tid = (int)threadIdx.x;
    const int lane = tid & 31, wid = tid >> 5;
    const int bm = blockIdx.y * 128, bn = blockIdx.x * 128;
    const int mbase = (wid >> 2) * 64;   // 2 m-warps
    const int nbase = (wid & 3) * 32;    // 4 n-warps

    if (tid == 0) {
        #pragma unroll
        for (int s = 0; s < NSTAGE; s++) {
            MBAR_INIT(sb + s * 8, 1);          // full: tx-based
            MBAR_INIT(sb + 32 + s * 8, 256);   // empty: all threads arrive
        }
    }
    __syncthreads();

    // per-thread ldmatrix row offsets (within one operand sub-tile)
    uint32_t aOff[4]; int aSw[4];
    #pragma unroll
    for (int mb = 0; mb < 4; mb++) {
        const int r = mbase + mb * 16 + (lane & 15);
        aOff[mb] = (uint32_t)r * 128u; aSw[mb] = r & 7;
    }
    uint32_t bOff[2]; int bSw[2];
    #pragma unroll
    for (int nb = 0; nb < 2; nb++) {
        const int r = nbase + nb * 16 + (lane & 7) + ((lane >> 3) & 1) * 8;
        bOff[nb] = (uint32_t)r * 128u; bSw[nb] = r & 7;
    }
    const int hi16 = lane >> 4;

    float mix[4][4][4];
    #pragma unroll
    for (int i = 0; i < 4; i++)
        #pragma unroll
        for (int j = 0; j < 4; j++)
            #pragma unroll
            for (int r = 0; r < 4; r++) mix[i][j][r] = 0.0f;

    // producer iterator state (used by tid 0 only)
    int pe = 0, pop = 0, pkt = 0;

    auto issue = [&](int t) {
        if (pe >= P.n_edges) return;
        const EdgeInfo ei = P.e[pe];
        const int s = t % NSTAGE;
        if (t >= NSTAGE) {
            const int ph = ((t / NSTAGE) + 1) & 1;   // parity of prior consumption
            MBAR_WAIT(sb + 32 + s * 8, ph);
        }
        const uint32_t st = tile0 + (uint32_t)s * STAGE;
        MBAR_EXPECT_TX(sb + s * 8, STAGE);
        const int kg = pkt * 64;
        int ka = kg;
        const CUtensorMap* AH = &P.a_hi[ei.a0];
        const CUtensorMap* AL = &P.a_lo[ei.a0];
        if (kg >= 1024) { AH = &P.a_hi[ei.a1]; AL = &P.a_lo[ei.a1]; ka = kg - 1024; }
        const CUtensorMap* BH = ei.b_is_wb ? &P.wb_hi : &P.ws_hi;
        const CUtensorMap* BL = ei.b_is_wb ? &P.wb_lo : &P.ws_lo;
        const int by = ei.b_row_base + pop * 1024 + bn;
        TMA2D(st,           AH, ka, bm, sb + s * 8);
        TMA2D(st + 16384u,  AL, ka, bm, sb + s * 8);
        TMA2D(st + 32768u,  BH, kg, by, sb + s * 8);
        TMA2D(st + 49152u,  BL, kg, by, sb + s * 8);
        if (++pkt == ei.K / 64) { pkt = 0; if (++pop == 5) { pop = 0; ++pe; } }
    };

    if (tid == 0) { issue(0); issue(1); issue(2); }

    int t = 0;
    for (int e = 0; e < P.n_edges; e++) {
        const int layer = P.e[e].layer;
        const int nch = P.e[e].K / 64;

        for (int op = 0; op < 5; op++) {
            float c[4][4][4];
            #pragma unroll
            for (int i = 0; i < 4; i++)
                #pragma unroll
                for (int j = 0; j < 4; j++)
                    #pragma unroll
                    for (int r = 0; r < 4; r++) c[i][j][r] = 0.0f;

            for (int kt = 0; kt < nch; kt++) {
                const int s = t % NSTAGE;
                MBAR_WAIT(sb + s * 8, (t / NSTAGE) & 1);
                const uint32_t st = tile0 + (uint32_t)s * STAGE;

                #pragma unroll
                for (int ks = 0; ks < 4; ks++) {
                    uint32_t bh[2][4], bl[2][4];
                    #pragma unroll
                    for (int nb = 0; nb < 2; nb++) {
                        const uint32_t co =
                            (uint32_t)(((ks * 2 + hi16) ^ bSw[nb]) * 16);
                        ldsm4(st + 32768u + bOff[nb] + co, bh[nb]);
                        ldsm4(st + 49152u + bOff[nb] + co, bl[nb]);
                    }
                    #pragma unroll
                    for (int mb = 0; mb < 4; mb++) {
                        uint32_t ah[4], al[4];
                        const uint32_t co =
                            (uint32_t)(((ks * 2 + hi16) ^ aSw[mb]) * 16);
                        ldsm4(st + aOff[mb] + co, ah);
                        ldsm4(st + 16384u + aOff[mb] + co, al);
                        #pragma unroll
                        for (int n8 = 0; n8 < 4; n8++) {
                            const int nb = n8 >> 1, hf = n8 & 1;
                            mma16816(c[mb][n8], ah, bh[nb][hf], bh[nb][hf + 2]);
                            mma16816(c[mb][n8], ah, bl[nb][hf], bl[nb][hf + 2]);
                            mma16816(c[mb][n8], al, bh[nb][hf], bh[nb][hf + 2]);
                        }
                    }
                }
                MBAR_ARRIVE(sb + 32 + s * 8);
                if (tid == 0) issue(t + NSTAGE);
                t++;
            }

            // ------- epilogue: mix += geno * act(c + bias) -------
            const float wgt = __ldg(&geno[layer * 5 + op]);
            __syncthreads();
            if (tid < 128)
                sbias[tid] = __ldg(&bsv[((size_t)layer * 5 + op) * 1024 + bn + tid]);
            __syncthreads();

            #define MIX_LOOP(AEXPR)                                            \
                _Pragma("unroll")                                              \
                for (int mb = 0; mb < 4; mb++)                                 \
                _Pragma("unroll")                                              \
                for (int n8 = 0; n8 < 4; n8++)                                 \
                _Pragma("unroll")                                              \
                for (int r = 0; r < 4; r++) {                                  \
                    const float h = c[mb][n8][r] +                             \
                        sbias[nbase + n8 * 8 + (lane & 3) * 2 + (r & 1)];      \
                    mix[mb][n8][r] += wgt * (AEXPR);                           \
                }
            switch (op) {
                case 0: MIX_LOOP(h); break;
                case 1: MIX_LOOP(fmaxf(h, 0.0f)); break;
                case 2: MIX_LOOP(__fdividef(2.0f, 1.0f + __expf(-2.0f * h)) - 1.0f); break;
                case 3: MIX_LOOP(__fdividef(1.0f, 1.0f + __expf(-h))); break;
                default: MIX_LOOP(h > 0.0f ? h : 0.2f * h); break;
            }
            #undef MIX_LOOP
        }
    }

    // ------- write node output -------
    if (P.node_out_idx >= 0) {
        __nv_bfloat16* dh = g_x_hi[P.node_out_idx];
        __nv_bfloat16* dl = g_x_lo[P.node_out_idx];
        #pragma unroll
        for (int mb = 0; mb < 4; mb++)
            #pragma unroll
            for (int n8 = 0; n8 < 4; n8++)
                #pragma unroll
                for (int r = 0; r < 4; r++) {
                    const int m = bm + mbase + mb * 16 + (lane >> 2) + ((r >> 1) & 1) * 8;
                    const int n = bn + nbase + n8 * 8 + (lane & 3) * 2 + (r & 1);
                    const float v = mix[mb][n8][r];
                    const __nv_bfloat16 h = __float2bfloat16(v);
                    dh[(size_t)m * 1024 + n] = h;
                    dl[(size_t)m * 1024 + n] =
                        __float2bfloat16(v - __bfloat162float(h));
                }
    } else {
        #pragma unroll
        for (int mb = 0; mb < 4; mb++)
            #pragma unroll
            for (int n8 = 0; n8 < 4; n8++)
                #pragma unroll
                for (int r = 0; r < 4; r++) {
                    const int m = bm + mbase + mb * 16 + (lane >> 2) + ((r >> 1) & 1) * 8;
                    const int n = bn + nbase + n8 * 8 + (lane & 3) * 2 + (r & 1);
                    outp[(size_t)m * 1024 + n] = mix[mb][n8][r];
                }
    }
}

// --------------------------------- host -------------------------------------
typedef CUresult (*EncodeFn)(CUtensorMap*, CUtensorMapDataType, cuuint32_t, void*,
                             const cuuint64_t*, const cuuint64_t*, const cuuint32_t*,
                             const cuuint32_t*, CUtensorMapInterleave, CUtensorMapSwizzle,
                             CUtensorMapL2promotion, CUtensorMapFloatOOBfill);

static void make2d(EncodeFn enc, CUtensorMap* out, void* base,
                   uint64_t dim0, uint64_t dim1, uint64_t stride_b, uint32_t boxh) {
    cuuint64_t dims[2]    = {dim0, dim1};
    cuuint64_t strides[1] = {stride_b};
    cuuint32_t box[2]     = {64u, boxh};
    cuuint32_t es[2]      = {1u, 1u};
    enc(out, CU_TENSOR_MAP_DATA_TYPE_BFLOAT16, 2, base, dims, strides, box, es,
        CU_TENSOR_MAP_INTERLEAVE_NONE, CU_TENSOR_MAP_SWIZZLE_128B,
        CU_TENSOR_MAP_L2_PROMOTION_L2_128B, CU_TENSOR_MAP_FLOAT_OOB_FILL_NONE);
}

extern "C" void kernel_launch(void* const* d_in, const int* in_sizes, int n_in,
                              void* d_out, int out_size)
{
    const float *s0 = nullptr, *s1 = nullptr, *geno = nullptr;
    const float *Ws = nullptr, *Wb = nullptr, *bsv = nullptr;
    for (int i = 0; i < n_in; i++) {
        const long sz = (long)in_sizes[i];
        const float* p = (const float*)d_in[i];
        if      (sz == (long)BATCH * DDIM)   { if (!s0) s0 = p; else s1 = p; }
        else if (sz == 90L)                    geno = p;
        else if (sz == 73400320L)              Ws = p;
        else if (sz == 41943040L)              Wb = p;
        else if (sz == 92160L)                 bsv = p;
    }

    void *ws_hi, *ws_lo, *wb_hi, *wb_lo, *x_hi, *x_lo;
    cudaGetSymbolAddress(&ws_hi, g_ws_hi);
    cudaGetSymbolAddress(&ws_lo, g_ws_lo);
    cudaGetSymbolAddress(&wb_hi, g_wb_hi);
    cudaGetSymbolAddress(&wb_lo, g_wb_lo);
    cudaGetSymbolAddress(&x_hi,  g_x_hi);
    cudaGetSymbolAddress(&x_lo,  g_x_lo);

    void* fp = nullptr;
    cudaDriverEntryPointQueryResult qres;
    cudaGetDriverEntryPointByVersion("cuTensorMapEncodeTiled", &fp, 12000,
                                     cudaEnableDefault, &qres);
    EncodeFn enc = (EncodeFn)fp;

    NodeP base;
    for (int i = 0; i < 5; i++) {
        make2d(enc, &base.a_hi[i], (char*)x_hi + (size_t)i * 4194304 * 2, 1024, 4096, 2048, 128);
        make2d(enc, &base.a_lo[i], (char*)x_lo + (size_t)i * 4194304 * 2, 1024, 4096, 2048, 128);
    }
    make2d(enc, &base.ws_hi, ws_hi, 1024, 71680, 2048, 128);
    make2d(enc, &base.ws_lo, ws_lo, 1024, 71680, 2048, 128);
    make2d(enc, &base.wb_hi, wb_hi, 2048, 20480, 4096, 128);
    make2d(enc, &base.wb_lo, wb_lo, 2048, 20480, 4096, 128);

    // conversions
    cvt_in<<<16384, 256>>>(s0, 0);
    cvt_in<<<16384, 256>>>(s1, 1);
    dim3 tb(32, 8);
    cvt_w<<<dim3(32, 32, 70), tb>>>(Ws, (__nv_bfloat16*)ws_hi, (__nv_bfloat16*)ws_lo, 1024);
    cvt_w<<<dim3(64, 32, 20), tb>>>(Wb, (__nv_bfloat16*)wb_hi, (__nv_bfloat16*)wb_lo, 2048);

    cudaFuncSetAttribute(gemm_node, cudaFuncAttributeMaxDynamicSharedMemorySize, DYN_SMEM);

    dim3 grid(8, 32), blk(256);
    int si = 0, bi = 0, offset = 0;
    for (int node = 0; node < 4; node++) {
        NodeP P = base;
        P.n_edges = node + 3;
        for (int j = 0; j < node + 3; j++) {
            EdgeInfo& e = P.e[j];
            e.layer = offset + j;
            if (j == 2) {
                e.b_is_wb = 1; e.b_row_base = bi * 5 * 1024; bi++;
                e.K = 2048; e.a0 = 0; e.a1 = 1;
            } else {
                e.b_is_wb = 0; e.b_row_base = si * 5 * 1024; si++;
                e.K = 1024;
                e.a0 = e.a1 = (j < 2) ? j : (j - 1);
            }
        }
        P.node_out_idx = (node < 3) ? (2 + node) : -1;
        gemm_node<<<grid, blk, DYN_SMEM>>>(P, geno, bsv, (float*)d_out);
        offset += node + 3;
    }
}

// round 7
// speedup vs baseline: 8.6121x; 2.4701x over previous
#include <cuda_runtime.h>
#include <cuda.h>
#include <cuda_fp16.h>
#include <math.h>
#include <stdint.h>

#define BATCH 4096
#define DDIM  1024
#define NSTAGE 4
#define STAGE  32768u
#define DYN_SMEM (2048u + NSTAGE * STAGE)

// ------------------------- device scratch (no cudaMalloc) -------------------
__device__ __half g_ws[73400320];     // [14*5][n=1024][k=1024]
__device__ __half g_wb[41943040];     // [4*5][n=1024][k=2048]
__device__ __half g_x[5][4194304];    // s0,s1,n0,n1,n2: [4096][1024]

// ------------------------------ PTX helpers ---------------------------------
__device__ __forceinline__ uint32_t smem_u32(const void* p) {
    uint32_t a;
    asm("{ .reg .u64 t; cvta.to.shared.u64 t, %1; cvt.u32.u64 %0, t; }"
        : "=r"(a) : "l"(p));
    return a;
}

#define MBAR_INIT(addr, cnt) \
    asm volatile("mbarrier.init.shared.b64 [%0], %1;" :: "r"(addr), "r"((uint32_t)(cnt)) : "memory")
#define MBAR_EXPECT_TX(addr, bytes) \
    asm volatile("mbarrier.arrive.expect_tx.shared.b64 _, [%0], %1;" :: "r"(addr), "r"((uint32_t)(bytes)) : "memory")
#define MBAR_ARRIVE(addr) \
    asm volatile("mbarrier.arrive.shared.b64 _, [%0];" :: "r"(addr) : "memory")
#define MBAR_WAIT(addr, ph) do {                                              \
    asm volatile(                                                             \
        "{\n\t.reg .pred P1;\n\t"                                             \
        "WL_%=:\n\t"                                                          \
        "mbarrier.try_wait.parity.acquire.cta.shared::cta.b64 P1, [%0], %1, 0x989680;\n\t" \
        "@P1 bra.uni WD_%=;\n\t"                                              \
        "bra.uni WL_%=;\n\t"                                                  \
        "WD_%=:\n\t}"                                                         \
        :: "r"((uint32_t)(addr)), "r"((uint32_t)(ph)) : "memory");            \
} while (0)

#define TMA2D(smaddr, map, cx, cy, mbar) \
    asm volatile("cp.async.bulk.tensor.2d.shared::cta.global.tile.mbarrier::complete_tx::bytes " \
                 "[%0], [%1, {%2, %3}], [%4];" \
                 :: "r"(smaddr), "l"(map), "r"(cx), "r"(cy), "r"(mbar) : "memory")

__device__ __forceinline__ void ldsm4(uint32_t addr, uint32_t r[4]) {
    asm volatile("ldmatrix.sync.aligned.m8n8.x4.shared.b16 {%0,%1,%2,%3}, [%4];"
        : "=r"(r[0]), "=r"(r[1]), "=r"(r[2]), "=r"(r[3]) : "r"(addr));
}

__device__ __forceinline__ void mma16816(float c[4], const uint32_t a[4],
                                         uint32_t b0, uint32_t b1) {
    asm volatile("mma.sync.aligned.m16n8k16.row.col.f32.f16.f16.f32 "
        "{%0,%1,%2,%3}, {%4,%5,%6,%7}, {%8,%9}, {%0,%1,%2,%3};"
        : "+f"(c[0]), "+f"(c[1]), "+f"(c[2]), "+f"(c[3])
        : "r"(a[0]), "r"(a[1]), "r"(a[2]), "r"(a[3]), "r"(b0), "r"(b1));
}

// ------------------------------- structs ------------------------------------
struct EdgeInfo {
    int a0, a1;        // g_x index for k<1024 / k>=1024
    int b_is_wb;       // 0: g_ws, 1: g_wb
    int b_row_base;    // tensor-local row base (idx*5*1024)
    int K;             // 1024 or 2048
    int layer;         // global layer index
};
struct NodeP {
    CUtensorMap a_map[5];
    CUtensorMap ws_map, wb_map;
    EdgeInfo e[6];
    int n_edges;
    int node_out_idx;  // 2..4 -> g_x dest, -1 -> final fp32 out
};

// --------------------------- conversion kernels -----------------------------
__global__ void cvt_in(const float* __restrict__ s, int idx) {
    int i = blockIdx.x * 256 + threadIdx.x;
    g_x[idx][i] = __float2half(s[i]);
}

// src: [Z][K][1024] fp32 -> dst: [Z][1024][K] fp16 (transpose)
__global__ void cvt_w(const float* __restrict__ src,
                      __half* __restrict__ dst, int K) {
    __shared__ float t[32][33];
    const int z = blockIdx.z;
    const int k0 = blockIdx.x * 32, n0 = blockIdx.y * 32;
    const int tx = threadIdx.x, ty = threadIdx.y;   // (32, 8)
    const float* s = src + (size_t)z * K * 1024;
    #pragma unroll
    for (int r = 0; r < 4; r++)
        t[ty + 8 * r][tx] = s[(size_t)(k0 + ty + 8 * r) * 1024 + n0 + tx];
    __syncthreads();
    const size_t dbase = (size_t)z * 1024 * K;
    #pragma unroll
    for (int r = 0; r < 4; r++) {
        const int n = n0 + ty + 8 * r, k = k0 + tx;
        dst[dbase + (size_t)n * K + k] = __float2half(t[tx][ty + 8 * r]);
    }
}

// ------------------------------ GEMM kernel ---------------------------------
__global__ void __launch_bounds__(256, 1)
gemm_node(const __grid_constant__ NodeP P,
          const float* __restrict__ geno,
          const float* __restrict__ bsv,
          float* __restrict__ outp)
{
    extern __shared__ char dynsmem[];
    const uint32_t sb = smem_u32(dynsmem);
    const uint32_t tile0 = (sb + 2047u) & ~1023u;
    float* sbias = (float*)(dynsmem + 256);
    const int tid = (int)threadIdx.x;
    const int lane = tid & 31, wid = tid >> 5;
    const int bm = blockIdx.y * 128, bn = blockIdx.x * 128;
    const int mbase = (wid >> 2) * 64;   // 2 m-warps
    const int nbase = (wid & 3) * 32;    // 4 n-warps

    if (tid == 0) {
        #pragma unroll
        for (int s = 0; s < NSTAGE; s++) {
            MBAR_INIT(sb + s * 8, 1);          // full: tx-based
            MBAR_INIT(sb + 64 + s * 8, 256);   // empty: all threads arrive
        }
    }
    __syncthreads();

    // per-thread ldmatrix row offsets (rows of 128B = 64 fp16)
    uint32_t aOff[4]; int aSw[4];
    #pragma unroll
    for (int mb = 0; mb < 4; mb++) {
        const int r = mbase + mb * 16 + (lane & 15);
        aOff[mb] = (uint32_t)r * 128u; aSw[mb] = r & 7;
    }
    uint32_t bOff[2]; int bSw[2];
    #pragma unroll
    for (int nb = 0; nb < 2; nb++) {
        const int r = nbase + nb * 16 + (lane & 7) + ((lane >> 3) & 1) * 8;
        bOff[nb] = (uint32_t)r * 128u; bSw[nb] = r & 7;
    }
    const int hi16 = lane >> 4;

    float mix[4][4][4];
    #pragma unroll
    for (int i = 0; i < 4; i++)
        #pragma unroll
        for (int j = 0; j < 4; j++)
            #pragma unroll
            for (int r = 0; r < 4; r++) mix[i][j][r] = 0.0f;

    // producer iterator state (tid 0 only)
    int pe = 0, pop = 0, pkt = 0;

    auto issue = [&](int t) {
        if (pe >= P.n_edges) return;
        const EdgeInfo ei = P.e[pe];
        const int s = t % NSTAGE;
        if (t >= NSTAGE) {
            const int ph = ((t / NSTAGE) + 1) & 1;
            MBAR_WAIT(sb + 64 + s * 8, ph);
        }
        const uint32_t st = tile0 + (uint32_t)s * STAGE;
        MBAR_EXPECT_TX(sb + s * 8, STAGE);
        const int kg = pkt * 64;
        int ka = kg;
        const CUtensorMap* A = &P.a_map[ei.a0];
        if (kg >= 1024) { A = &P.a_map[ei.a1]; ka = kg - 1024; }
        const CUtensorMap* B = ei.b_is_wb ? &P.wb_map : &P.ws_map;
        const int by = ei.b_row_base + pop * 1024 + bn;
        TMA2D(st,           A, ka, bm, sb + s * 8);
        TMA2D(st + 16384u,  B, kg, by, sb + s * 8);
        if (++pkt == ei.K / 64) { pkt = 0; if (++pop == 5) { pop = 0; ++pe; } }
    };

    if (tid == 0) {
        #pragma unroll
        for (int s = 0; s < NSTAGE; s++) issue(s);
    }

    int t = 0;
    for (int e = 0; e < P.n_edges; e++) {
        const int layer = P.e[e].layer;
        const int nch = P.e[e].K / 64;

        for (int op = 0; op < 5; op++) {
            float c[4][4][4];
            #pragma unroll
            for (int i = 0; i < 4; i++)
                #pragma unroll
                for (int j = 0; j < 4; j++)
                    #pragma unroll
                    for (int r = 0; r < 4; r++) c[i][j][r] = 0.0f;

            for (int kt = 0; kt < nch; kt++) {
                const int s = t % NSTAGE;
                MBAR_WAIT(sb + s * 8, (t / NSTAGE) & 1);
                const uint32_t st = tile0 + (uint32_t)s * STAGE;

                #pragma unroll
                for (int ks = 0; ks < 4; ks++) {
                    uint32_t bfrag[2][4];
                    #pragma unroll
                    for (int nb = 0; nb < 2; nb++) {
                        const uint32_t co =
                            (uint32_t)(((ks * 2 + hi16) ^ bSw[nb]) * 16);
                        ldsm4(st + 16384u + bOff[nb] + co, bfrag[nb]);
                    }
                    #pragma unroll
                    for (int mb = 0; mb < 4; mb++) {
                        uint32_t afrag[4];
                        const uint32_t co =
                            (uint32_t)(((ks * 2 + hi16) ^ aSw[mb]) * 16);
                        ldsm4(st + aOff[mb] + co, afrag);
                        #pragma unroll
                        for (int n8 = 0; n8 < 4; n8++) {
                            const int nb = n8 >> 1, hf = n8 & 1;
                            mma16816(c[mb][n8], afrag,
                                     bfrag[nb][hf], bfrag[nb][hf + 2]);
                        }
                    }
                }
                MBAR_ARRIVE(sb + 64 + s * 8);
                if (tid == 0) issue(t + NSTAGE);
                t++;
            }

            // ------- epilogue: mix += geno * act(c + bias) -------
            const float wgt = __ldg(&geno[layer * 5 + op]);
            __syncthreads();
            if (tid < 128)
                sbias[tid] = __ldg(&bsv[((size_t)layer * 5 + op) * 1024 + bn + tid]);
            __syncthreads();

            #define MIX_LOOP(AEXPR)                                            \
                _Pragma("unroll")                                              \
                for (int mb = 0; mb < 4; mb++)                                 \
                _Pragma("unroll")                                              \
                for (int n8 = 0; n8 < 4; n8++)                                 \
                _Pragma("unroll")                                              \
                for (int r = 0; r < 4; r++) {                                  \
                    const float h = c[mb][n8][r] +                             \
                        sbias[nbase + n8 * 8 + (lane & 3) * 2 + (r & 1)];      \
                    mix[mb][n8][r] += wgt * (AEXPR);                           \
                }
            switch (op) {
                case 0: MIX_LOOP(h); break;
                case 1: MIX_LOOP(fmaxf(h, 0.0f)); break;
                case 2: MIX_LOOP(__fdividef(2.0f, 1.0f + __expf(-2.0f * h)) - 1.0f); break;
                case 3: MIX_LOOP(__fdividef(1.0f, 1.0f + __expf(-h))); break;
                default: MIX_LOOP(h > 0.0f ? h : 0.2f * h); break;
            }
            #undef MIX_LOOP
        }
    }

    // ------- write node output -------
    if (P.node_out_idx >= 0) {
        __half* dh = g_x[P.node_out_idx];
        #pragma unroll
        for (int mb = 0; mb < 4; mb++)
            #pragma unroll
            for (int n8 = 0; n8 < 4; n8++)
                #pragma unroll
                for (int r = 0; r < 4; r++) {
                    const int m = bm + mbase + mb * 16 + (lane >> 2) + ((r >> 1) & 1) * 8;
                    const int n = bn + nbase + n8 * 8 + (lane & 3) * 2 + (r & 1);
                    dh[(size_t)m * 1024 + n] = __float2half(mix[mb][n8][r]);
                }
    } else {
        #pragma unroll
        for (int mb = 0; mb < 4; mb++)
            #pragma unroll
            for (int n8 = 0; n8 < 4; n8++)
                #pragma unroll
                for (int r = 0; r < 4; r++) {
                    const int m = bm + mbase + mb * 16 + (lane >> 2) + ((r >> 1) & 1) * 8;
                    const int n = bn + nbase + n8 * 8 + (lane & 3) * 2 + (r & 1);
                    outp[(size_t)m * 1024 + n] = mix[mb][n8][r];
                }
    }
}

// --------------------------------- host -------------------------------------
typedef CUresult (*EncodeFn)(CUtensorMap*, CUtensorMapDataType, cuuint32_t, void*,
                             const cuuint64_t*, const cuuint64_t*, const cuuint32_t*,
                             const cuuint32_t*, CUtensorMapInterleave, CUtensorMapSwizzle,
                             CUtensorMapL2promotion, CUtensorMapFloatOOBfill);

static void make2d(EncodeFn enc, CUtensorMap* out, void* base,
                   uint64_t dim0, uint64_t dim1, uint64_t stride_b, uint32_t boxh) {
    cuuint64_t dims[2]    = {dim0, dim1};
    cuuint64_t strides[1] = {stride_b};
    cuuint32_t box[2]     = {64u, boxh};
    cuuint32_t es[2]      = {1u, 1u};
    enc(out, CU_TENSOR_MAP_DATA_TYPE_FLOAT16, 2, base, dims, strides, box, es,
        CU_TENSOR_MAP_INTERLEAVE_NONE, CU_TENSOR_MAP_SWIZZLE_128B,
        CU_TENSOR_MAP_L2_PROMOTION_L2_128B, CU_TENSOR_MAP_FLOAT_OOB_FILL_NONE);
}

extern "C" void kernel_launch(void* const* d_in, const int* in_sizes, int n_in,
                              void* d_out, int out_size)
{
    const float *s0 = nullptr, *s1 = nullptr, *geno = nullptr;
    const float *Ws = nullptr, *Wb = nullptr, *bsv = nullptr;
    for (int i = 0; i < n_in; i++) {
        const long sz = (long)in_sizes[i];
        const float* p = (const float*)d_in[i];
        if      (sz == (long)BATCH * DDIM)   { if (!s0) s0 = p; else s1 = p; }
        else if (sz == 90L)                    geno = p;
        else if (sz == 73400320L)              Ws = p;
        else if (sz == 41943040L)              Wb = p;
        else if (sz == 92160L)                 bsv = p;
    }

    void *ws, *wb, *x;
    cudaGetSymbolAddress(&ws, g_ws);
    cudaGetSymbolAddress(&wb, g_wb);
    cudaGetSymbolAddress(&x,  g_x);

    void* fp = nullptr;
    cudaDriverEntryPointQueryResult qres;
    cudaGetDriverEntryPointByVersion("cuTensorMapEncodeTiled", &fp, 12000,
                                     cudaEnableDefault, &qres);
    EncodeFn enc = (EncodeFn)fp;

    NodeP base;
    for (int i = 0; i < 5; i++)
        make2d(enc, &base.a_map[i], (char*)x + (size_t)i * 4194304 * 2, 1024, 4096, 2048, 128);
    make2d(enc, &base.ws_map, ws, 1024, 71680, 2048, 128);
    make2d(enc, &base.wb_map, wb, 2048, 20480, 4096, 128);

    // conversions
    cvt_in<<<16384, 256>>>(s0, 0);
    cvt_in<<<16384, 256>>>(s1, 1);
    dim3 tb(32, 8);
    cvt_w<<<dim3(32, 32, 70), tb>>>(Ws, (__half*)ws, 1024);
    cvt_w<<<dim3(64, 32, 20), tb>>>(Wb, (__half*)wb, 2048);

    cudaFuncSetAttribute(gemm_node, cudaFuncAttributeMaxDynamicSharedMemorySize, DYN_SMEM);

    dim3 grid(8, 32), blk(256);
    int si = 0, bi = 0, offset = 0;
    for (int node = 0; node < 4; node++) {
        NodeP P = base;
        P.n_edges = node + 3;
        for (int j = 0; j < node + 3; j++) {
            EdgeInfo& e = P.e[j];
            e.layer = offset + j;
            if (j == 2) {
                e.b_is_wb = 1; e.b_row_base = bi * 5 * 1024; bi++;
                e.K = 2048; e.a0 = 0; e.a1 = 1;
            } else {
                e.b_is_wb = 0; e.b_row_base = si * 5 * 1024; si++;
                e.K = 1024;
                e.a0 = e.a1 = (j < 2) ? j : (j - 1);
            }
        }
        P.node_out_idx = (node < 3) ? (2 + node) : -1;
        gemm_node<<<grid, blk, DYN_SMEM>>>(P, geno, bsv, (float*)d_out);
        offset += node + 3;
    }
}